// round 13
// baseline (speedup 1.0000x reference)
#include <cuda_runtime.h>
#include <cstdint>

#define DEVINL __device__ __forceinline__

static constexpr int B_ = 32, N_ = 256, T_ = 1024, O_ = 1024, G_ = 8;

// 128 MB scratch for w_bot[b][o][t] (tf32-rounded fp32). Static __device__
// array per harness allocation rules.
__device__ float g_wbot[(size_t)B_ * O_ * T_];

// ---------------- helpers ----------------
DEVINL uint32_t smem_u32(const void* p) {
    uint32_t a;
    asm("{ .reg .u64 t; cvta.to.shared.u64 t, %1; cvt.u32.u64 %0, t; }" : "=r"(a) : "l"(p));
    return a;
}
DEVINL void cp_async16(uint32_t d, const void* g) {
    asm volatile("cp.async.cg.shared.global [%0], [%1], 16;" :: "r"(d), "l"(g) : "memory");
}
DEVINL void cp_commit() { asm volatile("cp.async.commit_group;" ::: "memory"); }
template <int NPend> DEVINL void cp_wait() {
    asm volatile("cp.async.wait_group %0;" :: "n"(NPend) : "memory");
}
DEVINL uint32_t tf32_rna_bits(float x) {
    uint32_t u;
    asm("cvt.rna.tf32.f32 %0, %1;" : "=r"(u) : "f"(x));
    return u;
}
// ldmatrix x4 on 32-bit data: each thread gets 4 consecutive bytes of a tile
// row, so tf32 elements are moved intact (no .trans anywhere).
DEVINL void ldsm_x4(uint32_t& r0, uint32_t& r1, uint32_t& r2, uint32_t& r3,
                    uint32_t addr) {
    asm volatile("ldmatrix.sync.aligned.m8n8.x4.shared.b16 {%0,%1,%2,%3}, [%4];"
                 : "=r"(r0), "=r"(r1), "=r"(r2), "=r"(r3) : "r"(addr));
}
DEVINL void mma_tf32(float& c0, float& c1, float& c2, float& c3,
                     uint32_t a0, uint32_t a1, uint32_t a2, uint32_t a3,
                     uint32_t b0, uint32_t b1) {
    asm volatile(
        "mma.sync.aligned.m16n8k8.row.col.f32.tf32.tf32.f32 "
        "{%0,%1,%2,%3}, {%4,%5,%6,%7}, {%8,%9}, {%0,%1,%2,%3};"
        : "+f"(c0), "+f"(c1), "+f"(c2), "+f"(c3)
        : "r"(a0), "r"(a1), "r"(a2), "r"(a3), "r"(b0), "r"(b1));
}

// ---------------- Pass 1: genre mixing ----------------
// w_bot[b,o,t] = sum_g y[b,g] * weight[g,o,t] * mask[o,t], rounded rna->tf32.
__global__ void __launch_bounds__(256) mix_kernel(const float* __restrict__ y,
                                                  const float* __restrict__ weight,
                                                  const float* __restrict__ mask) {
    __shared__ float ys[B_ * G_];  // 256
    const int tid = threadIdx.x;
    ys[tid] = y[tid];
    __syncthreads();

    const int idx = blockIdx.x * 256 + tid;  // over O*T/4
    const float4 mv = reinterpret_cast<const float4*>(mask)[idx];
    float4 wm[G_];
#pragma unroll
    for (int g = 0; g < G_; g++) {
        float4 w = reinterpret_cast<const float4*>(weight)[(size_t)g * (O_ * T_ / 4) + idx];
        wm[g].x = w.x * mv.x; wm[g].y = w.y * mv.y;
        wm[g].z = w.z * mv.z; wm[g].w = w.w * mv.w;
    }
    float4* wb = reinterpret_cast<float4*>(g_wbot) + idx;
#pragma unroll 4
    for (int b = 0; b < B_; b++) {
        float4 a = make_float4(0.f, 0.f, 0.f, 0.f);
#pragma unroll
        for (int g = 0; g < G_; g++) {
            const float yv = ys[b * G_ + g];
            a.x = fmaf(yv, wm[g].x, a.x);
            a.y = fmaf(yv, wm[g].y, a.y);
            a.z = fmaf(yv, wm[g].z, a.z);
            a.w = fmaf(yv, wm[g].w, a.w);
        }
        a.x = __uint_as_float(tf32_rna_bits(a.x));
        a.y = __uint_as_float(tf32_rna_bits(a.y));
        a.z = __uint_as_float(tf32_rna_bits(a.z));
        a.w = __uint_as_float(tf32_rna_bits(a.w));
        wb[(size_t)b * (O_ * T_ / 4)] = a;
    }
}

// ---------------- Pass 2: batched tf32 GEMM (mma.sync + ldmatrix) ----------
// out[b, m, o] = sum_t x[b,m,t] * w_bot[b,o,t] + bias[o]
// CTA tile: M=256 (all of N_), N=128, BK=32, 3 stages, 1 CTA/SM.
// 8 warps (256 thr): warp grid 4(m) x 2(n), warp tile 64x64.
// AI = 42.7 FLOP/B of smem traffic (2.7x the 128x128 tile) -> off the L2
// bandwidth ceiling that pinned tensor% at 49.
// A fed as raw fp32 bits (HW truncates to tf32); B pre-rounded rna in pass 1.
static constexpr int BM = 256, BN = 128, BK = 32, STAGES = 3;
static constexpr int LDSR = 36;                         // padded row: 32 + 4 floats
static constexpr int STAGE_FLOATS = (BM + BN) * LDSR;   // 13824 floats = 55296 B
static constexpr int NKT = T_ / BK;                     // 32 k-tiles
static constexpr uint32_t SMEM_BYTES = STAGES * STAGE_FLOATS * 4;  // 165888

DEVINL void load_stage(float* st, const float* __restrict__ gA,
                       const float* __restrict__ gB, int tid) {
    float* sA = st;
    float* sB = st + BM * LDSR;
#pragma unroll
    for (int i = 0; i < 8; i++) {  // A: 256 rows x 8 chunks = 2048 chunks
        const int v = tid + i * 256;
        const int row = v >> 3, c = v & 7;
        cp_async16(smem_u32(sA + row * LDSR + c * 4), gA + (size_t)row * T_ + c * 4);
    }
#pragma unroll
    for (int i = 0; i < 4; i++) {  // B: 128 rows x 8 chunks = 1024 chunks
        const int v = tid + i * 256;
        const int row = v >> 3, c = v & 7;
        cp_async16(smem_u32(sB + row * LDSR + c * 4), gB + (size_t)row * T_ + c * 4);
    }
}

__global__ void __launch_bounds__(256, 1)
gemm_kernel(const float* __restrict__ x, const float* __restrict__ bias,
            float* __restrict__ out) {
    extern __shared__ float smem[];
    const uint32_t sbase = smem_u32(smem);
    const int tid = threadIdx.x;
    const int wid = tid >> 5, lane = tid & 31;
    const int lq = lane >> 2, lr = lane & 3;  // quad row, quad col (epilogue)
    const int wm = wid & 3, wn = wid >> 2;    // warp m (0..3), warp n (0..1)
    const int b = blockIdx.y;
    const int o0 = blockIdx.x * BN;

    const float* gA = x + (size_t)b * N_ * T_;               // [256, T]
    const float* gB = g_wbot + ((size_t)b * O_ + o0) * T_;   // [128, T]

    const int m_base = wm * 64;
    const int n_base = wn * 64;

    // ldmatrix per-lane source coordinates (tile j = lane>>3, row i = lane&7):
    // A x4 tiles for (mf,kk): j&1 -> +8 rows, j>>1 -> +4 k.
    const int aRow = m_base + ((lane >> 3) & 1) * 8 + (lane & 7);
    const int aK   = (lane >> 4) * 4;
    // B x4 tiles for nf-pair: j&1 -> +4 k, j>>1 -> +8 n-rows.
    const int bRow = n_base + (lane >> 4) * 8 + (lane & 7);
    const int bK   = ((lane >> 3) & 1) * 4;
    const uint32_t aOff = (uint32_t)(aRow * LDSR + aK) * 4u;
    const uint32_t bOff = (uint32_t)(BM * LDSR + bRow * LDSR + bK) * 4u;

    float acc[4][8][4];
#pragma unroll
    for (int i = 0; i < 4; i++)
#pragma unroll
        for (int j = 0; j < 8; j++)
#pragma unroll
            for (int k = 0; k < 4; k++) acc[i][j][k] = 0.f;

    // Prologue: fill stages 0..STAGES-2
#pragma unroll
    for (int s = 0; s < STAGES - 1; s++) {
        load_stage(smem + s * STAGE_FLOATS, gA + s * BK, gB + s * BK, tid);
        cp_commit();
    }

    for (int kt = 0; kt < NKT; kt++) {
        cp_wait<STAGES - 2>();
        __syncthreads();  // also protects stage slot reuse (distance = STAGES)

        // Issue next stage load (overlaps with compute below)
        if (kt + STAGES - 1 < NKT) {
            const int kn = kt + STAGES - 1;
            load_stage(smem + (kn % STAGES) * STAGE_FLOATS,
                       gA + (size_t)kn * BK, gB + (size_t)kn * BK, tid);
        }
        cp_commit();

        const uint32_t stg = sbase + (uint32_t)((kt % STAGES) * STAGE_FLOATS) * 4u;
        const uint32_t aBase = stg + aOff;
        const uint32_t bBase = stg + bOff;

#pragma unroll
        for (int kk = 0; kk < 4; kk++) {
            uint32_t a[4][4];
#pragma unroll
            for (int mf = 0; mf < 4; mf++)
                ldsm_x4(a[mf][0], a[mf][1], a[mf][2], a[mf][3],
                        aBase + (uint32_t)(mf * 16 * LDSR + kk * 8) * 4u);
            uint32_t bf[8][2];
#pragma unroll
            for (int nfp = 0; nfp < 4; nfp++)
                ldsm_x4(bf[2 * nfp][0], bf[2 * nfp][1],
                        bf[2 * nfp + 1][0], bf[2 * nfp + 1][1],
                        bBase + (uint32_t)(nfp * 16 * LDSR + kk * 8) * 4u);
#pragma unroll
            for (int mf = 0; mf < 4; mf++)
#pragma unroll
                for (int nf = 0; nf < 8; nf++)
                    mma_tf32(acc[mf][nf][0], acc[mf][nf][1],
                             acc[mf][nf][2], acc[mf][nf][3],
                             a[mf][0], a[mf][1], a[mf][2], a[mf][3],
                             bf[nf][0], bf[nf][1]);
        }
    }

    // Epilogue: registers -> global with bias (float2 stores).
    float* outp = out + ((size_t)b * N_ + m_base) * O_ + o0 + n_base;
    const float* bp = bias + o0 + n_base;
#pragma unroll
    for (int nf = 0; nf < 8; nf++) {
        const int col = nf * 8 + lr * 2;
        const float bv0 = __ldg(bp + col);
        const float bv1 = __ldg(bp + col + 1);
#pragma unroll
        for (int mf = 0; mf < 4; mf++) {
            const int r = mf * 16 + lq;
            float2 v0 = make_float2(acc[mf][nf][0] + bv0, acc[mf][nf][1] + bv1);
            float2 v1 = make_float2(acc[mf][nf][2] + bv0, acc[mf][nf][3] + bv1);
            *reinterpret_cast<float2*>(outp + (size_t)r * O_ + col) = v0;
            *reinterpret_cast<float2*>(outp + (size_t)(r + 8) * O_ + col) = v1;
        }
    }
}

// ---------------- launch ----------------
extern "C" void kernel_launch(void* const* d_in, const int* in_sizes, int n_in,
                              void* d_out, int out_size) {
    const float* x      = (const float*)d_in[0];  // [B,N,T]
    const float* y      = (const float*)d_in[1];  // [B,G]
    const float* weight = (const float*)d_in[2];  // [G,O,T]
    const float* mask   = (const float*)d_in[3];  // [O,T]
    const float* bias   = (const float*)d_in[4];  // [O]
    float* out = (float*)d_out;                   // [B,N,O]

    mix_kernel<<<(O_ * T_ / 4) / 256, 256>>>(y, weight, mask);

    cudaFuncSetAttribute(gemm_kernel, cudaFuncAttributeMaxDynamicSharedMemorySize,
                         SMEM_BYTES);
    dim3 grid(O_ / BN, B_);
    gemm_kernel<<<grid, 256, SMEM_BYTES>>>(x, bias, out);
}

// round 16
// speedup vs baseline: 1.2168x; 1.2168x over previous
#include <cuda_runtime.h>
#include <cstdint>

#define DEVINL __device__ __forceinline__

static constexpr int B_ = 32, N_ = 256, T_ = 1024, O_ = 1024, G_ = 8;

// Scratch: w_bot in swizzled 128x32 tiles (128 MB) + x re-tiled (32 MB).
__device__ float g_wbot[(size_t)B_ * O_ * T_];
__device__ float g_xt[(size_t)B_ * N_ * T_];

// ---------------- helpers ----------------
DEVINL uint32_t smem_u32(const void* p) {
    uint32_t a;
    asm("{ .reg .u64 t; cvta.to.shared.u64 t, %1; cvt.u32.u64 %0, t; }" : "=r"(a) : "l"(p));
    return a;
}
DEVINL uint32_t tf32_rna_bits(float x) {
    uint32_t u;
    asm("cvt.rna.tf32.f32 %0, %1;" : "=r"(u) : "f"(x));
    return u;
}
DEVINL void ldsm_x4(uint32_t& r0, uint32_t& r1, uint32_t& r2, uint32_t& r3,
                    uint32_t addr) {
    asm volatile("ldmatrix.sync.aligned.m8n8.x4.shared.b16 {%0,%1,%2,%3}, [%4];"
                 : "=r"(r0), "=r"(r1), "=r"(r2), "=r"(r3) : "r"(addr));
}
DEVINL void mma_tf32(float& c0, float& c1, float& c2, float& c3,
                     uint32_t a0, uint32_t a1, uint32_t a2, uint32_t a3,
                     uint32_t b0, uint32_t b1) {
    asm volatile(
        "mma.sync.aligned.m16n8k8.row.col.f32.tf32.tf32.f32 "
        "{%0,%1,%2,%3}, {%4,%5,%6,%7}, {%8,%9}, {%0,%1,%2,%3};"
        : "+f"(c0), "+f"(c1), "+f"(c2), "+f"(c3)
        : "r"(a0), "r"(a1), "r"(a2), "r"(a3), "r"(b0), "r"(b1));
}
DEVINL void mbar_init(uint32_t a, uint32_t c) {
    asm volatile("mbarrier.init.shared.b64 [%0], %1;" :: "r"(a), "r"(c) : "memory");
}
DEVINL void mbar_expect_tx(uint32_t a, uint32_t tx) {
    asm volatile("mbarrier.arrive.expect_tx.shared.b64 _, [%0], %1;"
                 :: "r"(a), "r"(tx) : "memory");
}
DEVINL void mbar_wait(uint32_t a, uint32_t parity) {
    asm volatile(
        "{\n\t.reg .pred P;\n\t"
        "WL_%=:\n\t"
        "mbarrier.try_wait.parity.acquire.cta.shared::cta.b64 P, [%0], %1, 0x989680;\n\t"
        "@P bra.uni WD_%=;\n\t"
        "bra.uni WL_%=;\n\t"
        "WD_%=:\n\t}"
        :: "r"(a), "r"(parity) : "memory");
}
// Bulk async copy gmem->smem, mbarrier transaction completion (sm_90+).
DEVINL void bulk_g2s(uint32_t dst, const void* src, uint32_t bytes, uint32_t mbar) {
    asm volatile(
        "cp.async.bulk.shared::cta.global.mbarrier::complete_tx::bytes [%0], [%1], %2, [%3];"
        :: "r"(dst), "l"(src), "r"(bytes), "r"(mbar) : "memory");
}
DEVINL void fence_async_shared() { asm volatile("fence.proxy.async.shared::cta;" ::: "memory"); }

// Tile layout: [128 rows r][32 cols c] floats, 16 KB contiguous, with XOR
// swizzle: float4-granule g = (c>>2) stored at granule (g ^ (r&7)) within the
// row. Makes ldmatrix 8-row phases bank-conflict-free without padding.
DEVINL uint32_t tile_f4_off(int r, int c) {  // float offset of the float4 at (r, c&~3)
    return (uint32_t)(r * 32 + ((((c >> 2) & 7) ^ (r & 7)) << 2));
}

// ---------------- Pass 0: re-tile x into swizzled 16KB tiles ----------------
// g_xt tile index = (b*2 + (m>>7))*32 + (t>>5)
__global__ void __launch_bounds__(256) xtile_kernel(const float* __restrict__ x) {
    const int idx = blockIdx.x * 256 + threadIdx.x;      // over B*N*T/4
    const float4 v = reinterpret_cast<const float4*>(x)[idx];
    const int b = idx >> 16;            // N*T/4 = 65536
    const int rem = idx & 65535;
    const int m = rem >> 8;             // T/4 = 256 groups per row
    const int t = (rem & 255) << 2;
    const int tile = (b * 2 + (m >> 7)) * 32 + (t >> 5);
    float* dst = g_xt + (size_t)tile * 4096 + tile_f4_off(m & 127, t & 31);
    *reinterpret_cast<float4*>(dst) = v;
}

// ---------------- Pass 1: genre mixing -> swizzled tiles ----------------
// w_bot[b,o,t] = sum_g y[b,g]*weight[g,o,t]*mask[o,t], rna->tf32, stored in
// tile (b*8 + (o>>7))*32 + (t>>5), swizzled position.
__global__ void __launch_bounds__(256) mix_kernel(const float* __restrict__ y,
                                                  const float* __restrict__ weight,
                                                  const float* __restrict__ mask) {
    __shared__ float ys[B_ * G_];
    const int tid = threadIdx.x;
    ys[tid] = y[tid];
    __syncthreads();

    const int idx = blockIdx.x * 256 + tid;  // over O*T/4
    const int o = idx >> 8;
    const int t = (idx & 255) << 2;
    const float4 mv = reinterpret_cast<const float4*>(mask)[idx];
    float4 wm[G_];
#pragma unroll
    for (int g = 0; g < G_; g++) {
        float4 w = reinterpret_cast<const float4*>(weight)[(size_t)g * (O_ * T_ / 4) + idx];
        wm[g].x = w.x * mv.x; wm[g].y = w.y * mv.y;
        wm[g].z = w.z * mv.z; wm[g].w = w.w * mv.w;
    }
    const uint32_t inoff = tile_f4_off(o & 127, t & 31);
    const int tbase = (o >> 7) * 32 + (t >> 5);
#pragma unroll 4
    for (int b = 0; b < B_; b++) {
        float4 a = make_float4(0.f, 0.f, 0.f, 0.f);
#pragma unroll
        for (int g = 0; g < G_; g++) {
            const float yv = ys[b * G_ + g];
            a.x = fmaf(yv, wm[g].x, a.x);
            a.y = fmaf(yv, wm[g].y, a.y);
            a.z = fmaf(yv, wm[g].z, a.z);
            a.w = fmaf(yv, wm[g].w, a.w);
        }
        a.x = __uint_as_float(tf32_rna_bits(a.x));
        a.y = __uint_as_float(tf32_rna_bits(a.y));
        a.z = __uint_as_float(tf32_rna_bits(a.z));
        a.w = __uint_as_float(tf32_rna_bits(a.w));
        float* dst = g_wbot + ((size_t)(b * 8) + 0) * 0  // (kept simple below)
                     + (size_t)((b * 8 + (o >> 7)) * 32 + (t >> 5) - tbase + tbase) * 4096
                     + inoff;
        *reinterpret_cast<float4*>(dst) = a;
    }
}

// ---------------- Pass 2: batched tf32 GEMM, bulk-copy pipeline ----------
// out[b, m, o] = sum_t x[b,m,t] * w_bot[b,o,t] + bias[o]
// CTA tile 128x128x32, 4 warps (64x64 warp tile), 3 stages, 2 CTAs/SM.
// Stage fill = 2 x cp.async.bulk (16KB A tile + 16KB B tile) -> no LDGSTS.
static constexpr int BK = 32, STAGES = 3, NKT = T_ / BK;
static constexpr uint32_t STAGE_BYTES = 32768;           // A 16K + B 16K
static constexpr uint32_t MB_OFF = STAGES * STAGE_BYTES; // 98304
static constexpr uint32_t SMEM_BYTES = MB_OFF + 64;

__global__ void __launch_bounds__(128, 2)
gemm_kernel(const float* __restrict__ bias, float* __restrict__ out) {
    extern __shared__ float smem[];
    const uint32_t sbase = smem_u32(smem);
    const int tid = threadIdx.x;
    const int lane = tid & 31, wid = tid >> 5;
    const int lq = lane >> 2, lr = lane & 3;
    const int wm = wid & 1, wn = wid >> 1;
    const int b = blockIdx.z;
    const int ot = blockIdx.x;           // o-tile (128)
    const int mt = blockIdx.y;           // m-tile (128)

    const float* gA = g_xt + (size_t)((b * 2 + mt) * 32) * 4096;
    const float* gB = g_wbot + (size_t)((b * 8 + ot) * 32) * 4096;

    const int m_base = wm * 64;
    const int n_base = wn * 64;

    // Per-lane LDSM source addresses (byte offsets within a tile), swizzled.
    // A lane: row = m_base + ((lane>>3)&1)*8 + (lane&7), granule g0 = lane>>4.
    const int aR = m_base + ((lane >> 3) & 1) * 8 + (lane & 7);
    const int ag0 = lane >> 4;
    // B lane: row = n_base + (lane>>4)*8 + (lane&7), granule g0 = (lane>>3)&1.
    const int bR = n_base + (lane >> 4) * 8 + (lane & 7);
    const int bg0 = (lane >> 3) & 1;
    uint32_t aOffkk[4], bOffkk[4];
#pragma unroll
    for (int kk = 0; kk < 4; kk++) {
        aOffkk[kk] = (uint32_t)(aR * 128 + (((ag0 + 2 * kk) ^ (aR & 7)) << 4));
        bOffkk[kk] = 16384u + (uint32_t)(bR * 128 + (((bg0 + 2 * kk) ^ (bR & 7)) << 4));
    }

    float acc[4][8][4];
#pragma unroll
    for (int i = 0; i < 4; i++)
#pragma unroll
        for (int j = 0; j < 8; j++)
#pragma unroll
            for (int k = 0; k < 4; k++) acc[i][j][k] = 0.f;

    // mbarrier init + prologue fills
    if (tid == 0) {
        for (int s = 0; s < STAGES; s++) mbar_init(MB_OFF + sbase + 8 * s, 1);
    }
    __syncthreads();
    if (tid == 0) {
#pragma unroll
        for (int s = 0; s < STAGES; s++) {
            const uint32_t mb = sbase + MB_OFF + 8 * s;
            mbar_expect_tx(mb, STAGE_BYTES);
            bulk_g2s(sbase + s * STAGE_BYTES, gA + (size_t)s * 4096, 16384, mb);
            bulk_g2s(sbase + s * STAGE_BYTES + 16384, gB + (size_t)s * 4096, 16384, mb);
        }
    }

    for (int kt = 0; kt < NKT; kt++) {
        const int s = kt % STAGES;
        const uint32_t mb = sbase + MB_OFF + 8 * s;
        mbar_wait(mb, (uint32_t)((kt / STAGES) & 1));

        const uint32_t stg = sbase + (uint32_t)s * STAGE_BYTES;
#pragma unroll
        for (int kk = 0; kk < 4; kk++) {
            uint32_t a[4][4];
#pragma unroll
            for (int mf = 0; mf < 4; mf++)
                ldsm_x4(a[mf][0], a[mf][1], a[mf][2], a[mf][3],
                        stg + aOffkk[kk] + (uint32_t)(mf * 2048));
            uint32_t bf[8][2];
#pragma unroll
            for (int nfp = 0; nfp < 4; nfp++)
                ldsm_x4(bf[2 * nfp][0], bf[2 * nfp][1],
                        bf[2 * nfp + 1][0], bf[2 * nfp + 1][1],
                        stg + bOffkk[kk] + (uint32_t)(nfp * 2048));
#pragma unroll
            for (int mf = 0; mf < 4; mf++)
#pragma unroll
                for (int nf = 0; nf < 8; nf++)
                    mma_tf32(acc[mf][nf][0], acc[mf][nf][1],
                             acc[mf][nf][2], acc[mf][nf][3],
                             a[mf][0], a[mf][1], a[mf][2], a[mf][3],
                             bf[nf][0], bf[nf][1]);
        }

        __syncthreads();  // all warps done reading stage s
        if (tid == 0 && kt + STAGES < NKT) {
            fence_async_shared();
            const int kn = kt + STAGES;
            mbar_expect_tx(mb, STAGE_BYTES);
            bulk_g2s(stg, gA + (size_t)kn * 4096, 16384, mb);
            bulk_g2s(stg + 16384, gB + (size_t)kn * 4096, 16384, mb);
        }
    }

    // Epilogue: registers -> global with bias (float2 stores).
    float* outp = out + ((size_t)b * N_ + mt * 128 + m_base) * O_ + ot * 128 + n_base;
    const float* bp = bias + ot * 128 + n_base;
#pragma unroll
    for (int nf = 0; nf < 8; nf++) {
        const int col = nf * 8 + lr * 2;
        const float bv0 = __ldg(bp + col);
        const float bv1 = __ldg(bp + col + 1);
#pragma unroll
        for (int mf = 0; mf < 4; mf++) {
            const int r = mf * 16 + lq;
            float2 v0 = make_float2(acc[mf][nf][0] + bv0, acc[mf][nf][1] + bv1);
            float2 v1 = make_float2(acc[mf][nf][2] + bv0, acc[mf][nf][3] + bv1);
            *reinterpret_cast<float2*>(outp + (size_t)r * O_ + col) = v0;
            *reinterpret_cast<float2*>(outp + (size_t)(r + 8) * O_ + col) = v1;
        }
    }
}

// ---------------- launch ----------------
extern "C" void kernel_launch(void* const* d_in, const int* in_sizes, int n_in,
                              void* d_out, int out_size) {
    const float* x      = (const float*)d_in[0];  // [B,N,T]
    const float* y      = (const float*)d_in[1];  // [B,G]
    const float* weight = (const float*)d_in[2];  // [G,O,T]
    const float* mask   = (const float*)d_in[3];  // [O,T]
    const float* bias   = (const float*)d_in[4];  // [O]
    float* out = (float*)d_out;                   // [B,N,O]

    xtile_kernel<<<(B_ * N_ * T_ / 4) / 256, 256>>>(x);
    mix_kernel<<<(O_ * T_ / 4) / 256, 256>>>(y, weight, mask);

    cudaFuncSetAttribute(gemm_kernel, cudaFuncAttributeMaxDynamicSharedMemorySize,
                         SMEM_BYTES);
    dim3 grid(O_ / 128, N_ / 128, B_);
    gemm_kernel<<<grid, 128, SMEM_BYTES>>>(bias, out);
}